// round 14
// baseline (speedup 1.0000x reference)
#include <cuda_runtime.h>
#include <cstdint>

#define N 8192
#define IN_F 512
#define OUT_F 64
#define SS 512

// ---------------- device scratch (static) ----------------
__device__ float g_R[N];                           // exp(-0.8 * s1_i)
__device__ __align__(16) float2 g_EP[N];           // (exp(s2_j), exp(0.2*s2_j))
__device__ __align__(16) float g_part[512 * N];    // 16MB per-block partial colsums
__device__ float g_colsumf[N];

// ---------------- PTX helpers (inlined) ----------------
__device__ __forceinline__ uint32_t smem_u32(const void* p) {
    uint32_t a;
    asm("{ .reg .u64 tmp; cvta.to.shared.u64 tmp, %1; cvt.u32.u64 %0, tmp; }"
        : "=r"(a) : "l"(p));
    return a;
}
#define MBARRIER_INIT(mbar, cnt) \
    asm volatile("mbarrier.init.shared.b64 [%0], %1;" :: "r"(mbar), "r"(cnt) : "memory")
#define MBARRIER_EXPECT_TX(mbar, bytes) \
    asm volatile("mbarrier.arrive.expect_tx.shared.b64 _, [%0], %1;" :: "r"(mbar), "r"(bytes) : "memory")
#define TMA_BULK_1D(dst, src, bytes, mbar) \
    asm volatile("cp.async.bulk.shared::cluster.global.mbarrier::complete_tx::bytes [%0], [%1], %2, [%3];" \
                 :: "r"(dst), "l"(src), "r"(bytes), "r"(mbar) : "memory")
#define MBARRIER_WAIT_PARITY(mbar, par) do {                                      \
    uint32_t _mb = (mbar), _pr = (par), _done;                                    \
    asm volatile("{\n\t.reg .pred p;\n\t"                                         \
        "mbarrier.try_wait.parity.acquire.cta.shared::cta.b64 p, [%1], %2;\n\t"   \
        "selp.b32 %0, 1, 0, p;\n\t}"                                              \
        : "=r"(_done) : "r"(_mb), "r"(_pr) : "memory");                           \
    if (!_done) {                                                                 \
        asm volatile("{\n\t.reg .pred P1;\n\t"                                    \
            "WL_%=:\n\t"                                                          \
            "mbarrier.try_wait.parity.acquire.cta.shared::cta.b64 P1, [%0], %1, 0x989680;\n\t" \
            "@P1 bra.uni WD_%=;\n\t"                                              \
            "bra.uni WL_%=;\n\t"                                                  \
            "WD_%=:\n\t}"                                                         \
            :: "r"(_mb), "r"(_pr) : "memory");                                    \
    }                                                                             \
} while (0)

// ---------------- s1,s2 = input @ (W@a)  ->  R_i, (ex_j, ey_j) ----------------
__global__ void k_s(const float* __restrict__ in, const float* __restrict__ W,
                    const float* __restrict__ a) {
    __shared__ float swa[2 * IN_F];
    int t = threadIdx.x;
#pragma unroll
    for (int half = 0; half < 2; half++) {
        int m = t + half * 256;
        const float4* w4 = (const float4*)(W + m * OUT_F);
        float s1 = 0.f, s2 = 0.f;
#pragma unroll
        for (int q = 0; q < OUT_F / 4; q++) {
            float4 wv = __ldg(w4 + q);
            s1 += wv.x * __ldg(a + 4 * q + 0) + wv.y * __ldg(a + 4 * q + 1)
                + wv.z * __ldg(a + 4 * q + 2) + wv.w * __ldg(a + 4 * q + 3);
            s2 += wv.x * __ldg(a + OUT_F + 4 * q + 0) + wv.y * __ldg(a + OUT_F + 4 * q + 1)
                + wv.z * __ldg(a + OUT_F + 4 * q + 2) + wv.w * __ldg(a + OUT_F + 4 * q + 3);
        }
        swa[m] = s1;
        swa[IN_F + m] = s2;
    }
    __syncthreads();

    int warp = t >> 5, lane = t & 31;
    int row = blockIdx.x * 8 + warp;
    const float* ir = in + (size_t)row * IN_F;
    float s1 = 0.f, s2 = 0.f;
#pragma unroll
    for (int q = 0; q < IN_F / 32; q++) {
        float x = __ldg(ir + q * 32 + lane);
        s1 = fmaf(x, swa[q * 32 + lane], s1);
        s2 = fmaf(x, swa[IN_F + q * 32 + lane], s2);
    }
#pragma unroll
    for (int o = 16; o; o >>= 1) {
        s1 += __shfl_xor_sync(0xFFFFFFFFu, s1, o);
        s2 += __shfl_xor_sync(0xFFFFFFFFu, s2, o);
    }
    if (lane == 0) {
        double d1 = (double)s1, d2 = (double)s2;
        g_R[row] = (float)exp(-0.8 * d1);
        g_EP[row] = make_float2((float)exp(d2), (float)exp(0.2 * d2));
    }
}

// ---------------- TMA-pipelined masked-softmax + column partial sums ----------------
// 512 blocks x 512 threads; block owns 16 rows; thread owns 16 fixed columns:
//   column(g,e) = g*2048 + 4t + e
// Adjacency rows stream through a 4-stage 32KB smem ring via cp.async.bulk;
// TMA runs 4 rows ahead of the per-row barrier -> in-flight bytes independent
// of warp count. Arithmetic order identical to R12 (bit-exact result).
#define STAGES 4
#define ROW_BYTES (N * 4)
#define SM_MBAR 0
#define SM_SZ 64
#define SM_STAGE 2048
#define SM_MAIN_TOTAL (SM_STAGE + STAGES * ROW_BYTES)

__global__ void __launch_bounds__(512, 1) k_main(const int* __restrict__ adj) {
    extern __shared__ char smem[];
    uint32_t sb = smem_u32(smem);
    float* sZ = (float*)(smem + SM_SZ);            // [16 rows][16 warps]
    int t = threadIdx.x;
    int warp = t >> 5, lane = t & 31;
    int row0 = blockIdx.x * 16;

    // this thread's 16 (ex, ey) pairs -> registers
    float ex[16], ey[16];
    const float4* ep4 = (const float4*)g_EP;
#pragma unroll
    for (int g = 0; g < 4; g++) {
#pragma unroll
        for (int q = 0; q < 2; q++) {
            float4 v = __ldg(ep4 + g * 1024 + 2 * t + q);
            ex[g * 4 + 2 * q + 0] = v.x; ey[g * 4 + 2 * q + 0] = v.y;
            ex[g * 4 + 2 * q + 1] = v.z; ey[g * 4 + 2 * q + 1] = v.w;
        }
    }

    if (t == 0) {
#pragma unroll
        for (int d = 0; d < STAGES; d++) MBARRIER_INIT(sb + SM_MBAR + 8 * d, 1);
    }
    __syncthreads();
    if (t == 0) {
#pragma unroll
        for (int d = 0; d < STAGES; d++) {
            uint32_t mb = sb + SM_MBAR + 8 * d;
            MBARRIER_EXPECT_TX(mb, ROW_BYTES);
            TMA_BULK_1D(sb + SM_STAGE + d * ROW_BYTES,
                        (const void*)(adj + (size_t)(row0 + d) * N), ROW_BYTES, mb);
        }
    }

    float acc[16];
#pragma unroll
    for (int k = 0; k < 16; k++) acc[k] = 0.f;

    for (int r = 0; r < 16; r++) {
        int s = r & 3;
        MBARRIER_WAIT_PARITY(sb + SM_MBAR + 8 * s, (r >> 2) & 1);
        const int4* st = (const int4*)(smem + SM_STAGE + s * ROW_BYTES);
        float R = __ldg(g_R + row0 + r);
        float w[16];
        float z = 0.f;
#pragma unroll
        for (int g = 0; g < 4; g++) {
            int4 A = st[g * 512 + t];              // conflict-free LDS.128
            float w0 = fmaxf(ex[g * 4 + 0], R * ey[g * 4 + 0]);
            float w1 = fmaxf(ex[g * 4 + 1], R * ey[g * 4 + 1]);
            float w2 = fmaxf(ex[g * 4 + 2], R * ey[g * 4 + 2]);
            float w3 = fmaxf(ex[g * 4 + 3], R * ey[g * 4 + 3]);
            w0 = (A.x > 0) ? w0 : 0.f;
            w1 = (A.y > 0) ? w1 : 0.f;
            w2 = (A.z > 0) ? w2 : 0.f;
            w3 = (A.w > 0) ? w3 : 0.f;
            w[g * 4 + 0] = w0; w[g * 4 + 1] = w1;
            w[g * 4 + 2] = w2; w[g * 4 + 3] = w3;
            z += (w0 + w1) + (w2 + w3);            // same order as R12
        }
#pragma unroll
        for (int o = 16; o; o >>= 1) z += __shfl_xor_sync(0xFFFFFFFFu, z, o);
        if (lane == 0) sZ[r * 16 + warp] = z;
        __syncthreads();                           // all consumed stage s + sZ visible
        if (t == 0 && r + STAGES < 16) {           // refill stage s with row r+4
            uint32_t mb = sb + SM_MBAR + 8 * s;
            MBARRIER_EXPECT_TX(mb, ROW_BYTES);
            TMA_BULK_1D(sb + SM_STAGE + s * ROW_BYTES,
                        (const void*)(adj + (size_t)(row0 + r + STAGES) * N), ROW_BYTES, mb);
        }
        float zt = 0.f;
#pragma unroll
        for (int q = 0; q < 16; q++) zt += sZ[r * 16 + q];   // same order as R12
        float invZ = (zt > 0.f) ? (1.0f / zt) : 0.f;
#pragma unroll
        for (int k = 0; k < 16; k++) acc[k] = fmaf(w[k], invZ, acc[k]);
    }

    float4* part4 = (float4*)(g_part + (size_t)blockIdx.x * N);
#pragma unroll
    for (int g = 0; g < 4; g++)
        part4[g * 512 + t] = make_float4(acc[g * 4 + 0], acc[g * 4 + 1],
                                         acc[g * 4 + 2], acc[g * 4 + 3]);
}

// ---------------- deterministic column reduction (fp32 chunks, fp64 combine) ----
__global__ void __launch_bounds__(256) k_reduce() {
    __shared__ float sd[8][32];
    int t = threadIdx.x;
    int v = t & 31;
    int u = t >> 5;
    int c = blockIdx.x * 32 + v;
    float s = 0.f;
    int b0 = u * 64;
#pragma unroll 8
    for (int b = b0; b < b0 + 64; b++)
        s += g_part[(size_t)b * N + c];
    sd[u][v] = s;
    __syncthreads();
    if (u == 0) {
        double tot = 0.0;
#pragma unroll
        for (int q = 0; q < 8; q++) tot += (double)sd[q][v];
        g_colsumf[c] = (float)tot;
    }
}

// ---------------- exact top-512 via histogram select (1 block) ----------------
// Scores >= 0 -> uint bits order-preserving. Threshold on 12-bit prefix keeps
// ~600 candidates; candidate-relative rank == global rank (non-candidates have
// strictly smaller prefix). Exact (value desc, index asc) order.
__global__ void __launch_bounds__(1024) k_sel(float* __restrict__ out) {
    __shared__ uint32_t hist[4096];
    __shared__ uint32_t lvl1[128];
    __shared__ uint32_t thetaBin, cnt;
    __shared__ uint32_t cbits[2048];
    __shared__ uint16_t cidx[2048];
    int t = threadIdx.x;
#pragma unroll
    for (int i = t; i < 4096; i += 1024) hist[i] = 0;
    if (t == 0) cnt = 0;
    __syncthreads();

    uint32_t mybits[8];
#pragma unroll
    for (int q = 0; q < 8; q++) {
        uint32_t b = __float_as_uint(g_colsumf[q * 1024 + t]);
        mybits[q] = b;
        atomicAdd(&hist[b >> 19], 1u);
    }
    __syncthreads();

    if (t < 128) {
        uint32_t s = 0;
#pragma unroll
        for (int q = 0; q < 32; q++) s += hist[t * 32 + q];
        lvl1[t] = s;
    }
    __syncthreads();
    if (t == 0) {
        uint32_t acc = 0;
        int blk = 127;
        for (; blk > 0; blk--) {
            if (acc + lvl1[blk] >= SS) break;
            acc += lvl1[blk];
        }
        int b = blk * 32 + 31;
        for (; b > 0; b--) {
            acc += hist[b];
            if (acc >= SS) break;
        }
        thetaBin = (uint32_t)b;
    }
    __syncthreads();

    uint32_t B = thetaBin;
#pragma unroll
    for (int q = 0; q < 8; q++) {
        if ((mybits[q] >> 19) >= B) {
            uint32_t slot = atomicAdd(&cnt, 1u);
            if (slot < 2048) { cbits[slot] = mybits[q]; cidx[slot] = (uint16_t)(q * 1024 + t); }
        }
    }
    __syncthreads();

    int C = (int)min(cnt, 2048u);
    for (int i = t; i < C; i += 1024) {
        uint32_t bi = cbits[i];
        int ii = cidx[i];
        int r = 0;
        for (int q = 0; q < C; q++) {
            uint32_t bq = cbits[q];
            r += (bq > bi) || (bq == bi && cidx[q] < ii);
        }
        if (r < SS) out[r] = (float)ii;
    }
}

// ---------------- launch ----------------
extern "C" void kernel_launch(void* const* d_in, const int* in_sizes, int n_in,
                              void* d_out, int out_size) {
    const float* input = nullptr;
    const int*   adj   = nullptr;
    const float* W     = nullptr;
    const float* a     = nullptr;
    for (int i = 0; i < n_in; i++) {
        long long s = in_sizes[i];
        if      (s == (long long)N * IN_F)     input = (const float*)d_in[i];
        else if (s == (long long)N * N)        adj   = (const int*)d_in[i];
        else if (s == (long long)IN_F * OUT_F) W     = (const float*)d_in[i];
        else if (s == 2 * OUT_F)               a     = (const float*)d_in[i];
    }
    if (!input || !adj || !W || !a) {
        input = (const float*)d_in[0];
        adj   = (const int*)d_in[1];
        W     = (const float*)d_in[2];
        a     = (const float*)d_in[3];
    }
    float* out = (float*)d_out;

    cudaFuncSetAttribute(k_main, cudaFuncAttributeMaxDynamicSharedMemorySize,
                         SM_MAIN_TOTAL);

    k_s<<<N / 8, 256>>>(input, W, a);
    k_main<<<512, 512, SM_MAIN_TOTAL>>>(adj);
    k_reduce<<<N / 32, 256>>>();
    k_sel<<<1, 1024>>>(out);
}